// round 3
// baseline (speedup 1.0000x reference)
#include <cuda_runtime.h>
#include <cuda_bf16.h>
#include <math.h>

// Problem constants
#define BB   512
#define LL   128
#define DD   300
#define RR   256
#define SAA  256

// Scratch (device globals — no allocation allowed)
__device__ float g_Lseq[(size_t)BB * LL * RR];   // 67 MB
__device__ float g_G1  [(size_t)BB * LL * SAA]; // 67 MB
__device__ float g_G2  [(size_t)BB * LL * SAA]; // 67 MB
__device__ float g_t2T [SAA * RR];              // trans_r2 transposed: t2T[r][s] = tr2[s][r]

__device__ __forceinline__ float sigmoid_f(float x) {
    return 1.0f / (1.0f + __expf(-x));
}
__device__ __forceinline__ float tanh_f(float x) {
    // tanh(x) = 1 - 2/(exp(2x)+1); robust at extremes with __expf
    return 1.0f - 2.0f / (__expf(2.0f * x) + 1.0f);
}

// ---------------------------------------------------------------------------
// Kernel 0: transpose trans_r2 (SA x R) -> t2T (R x SA)
// ---------------------------------------------------------------------------
__global__ void transpose_tr2(const float* __restrict__ tr2) {
    int idx = blockIdx.x * 256 + threadIdx.x;   // 65536 threads
    int r = idx >> 8;
    int s = idx & 255;
    g_t2T[r * SAA + s] = tr2[s * RR + r];
}

// ---------------------------------------------------------------------------
// Kernel 1: token-parallel precompute.
//   Lseq = embed_r[id]*beta + tanh(emb[id] @ embed_r_gen)*(1-beta)
//   G1   = Lseq @ Wrs1 + bs1
//   G2   = Lseq @ Wrs2 + bs2
// Block = 16 tokens, 256 threads (thread = output column r / s).
// ---------------------------------------------------------------------------
#define TOK 16

__global__ __launch_bounds__(256) void precompute_kernel(
    const int*   __restrict__ ids,
    const float* __restrict__ embedding,   // V x D
    const float* __restrict__ embed_r,     // V x R
    const float* __restrict__ erg,         // D x R
    const float* __restrict__ Wrs1,        // R x SA
    const float* __restrict__ bs1,         // SA
    const float* __restrict__ Wrs2,        // R x SA
    const float* __restrict__ bs2,         // SA
    const float* __restrict__ beta)        // R
{
    __shared__ int   s_id[TOK];
    __shared__ float s_emb[TOK * 304];     // 300 padded to 304 (16B align per token)
    __shared__ float s_Lt[TOK * RR];

    const int tid  = threadIdx.x;
    const int tok0 = blockIdx.x * TOK;

    if (tid < TOK) s_id[tid] = ids[tok0 + tid];
    __syncthreads();

    // Gather embeddings (coalesced per token row)
    for (int i = tid; i < TOK * DD; i += 256) {
        int t = i / DD;
        int d = i - t * DD;
        s_emb[t * 304 + d] = embedding[(long)s_id[t] * DD + d];
    }
    __syncthreads();

    const int r = tid;
    const float beta_r = beta[r];

    // Lg = tanh(emb @ erg), per thread column r, 16 tokens at once
    float acc[TOK];
#pragma unroll
    for (int t = 0; t < TOK; t++) acc[t] = 0.0f;

    const float4* s_emb4 = reinterpret_cast<const float4*>(s_emb);
    for (int d4 = 0; d4 < DD / 4; d4++) {          // 300/4 = 75
        int d = d4 * 4;
        float w0 = erg[(d + 0) * RR + r];
        float w1 = erg[(d + 1) * RR + r];
        float w2 = erg[(d + 2) * RR + r];
        float w3 = erg[(d + 3) * RR + r];
#pragma unroll
        for (int t = 0; t < TOK; t++) {
            float4 e = s_emb4[t * 76 + d4];
            acc[t] += e.x * w0 + e.y * w1 + e.z * w2 + e.w * w3;
        }
    }

#pragma unroll
    for (int t = 0; t < TOK; t++) {
        float lg = tanh_f(acc[t]);
        float er = embed_r[(long)s_id[t] * RR + r];
        float v  = er * beta_r + lg * (1.0f - beta_r);
        s_Lt[t * RR + r] = v;
        g_Lseq[(long)(tok0 + t) * RR + r] = v;
    }
    __syncthreads();

    // G1 / G2 = Lseq @ Wrs{1,2} + bias
    float a1[TOK], a2[TOK];
    const float b1v = bs1[r];
    const float b2v = bs2[r];
#pragma unroll
    for (int t = 0; t < TOK; t++) { a1[t] = b1v; a2[t] = b2v; }

    const float4* s_Lt4 = reinterpret_cast<const float4*>(s_Lt);
    for (int k4 = 0; k4 < RR / 4; k4++) {
        int k = k4 * 4;
        float w10 = Wrs1[(k + 0) * SAA + r];
        float w11 = Wrs1[(k + 1) * SAA + r];
        float w12 = Wrs1[(k + 2) * SAA + r];
        float w13 = Wrs1[(k + 3) * SAA + r];
        float w20 = Wrs2[(k + 0) * SAA + r];
        float w21 = Wrs2[(k + 1) * SAA + r];
        float w22 = Wrs2[(k + 2) * SAA + r];
        float w23 = Wrs2[(k + 3) * SAA + r];
#pragma unroll
        for (int t = 0; t < TOK; t++) {
            float4 lv = s_Lt4[t * 64 + k4];
            a1[t] += lv.x * w10 + lv.y * w11 + lv.z * w12 + lv.w * w13;
            a2[t] += lv.x * w20 + lv.y * w21 + lv.z * w22 + lv.w * w23;
        }
    }

#pragma unroll
    for (int t = 0; t < TOK; t++) {
        g_G1[(long)(tok0 + t) * SAA + r] = a1[t];
        g_G2[(long)(tok0 + t) * SAA + r] = a2[t];
    }
}

// ---------------------------------------------------------------------------
// Kernel 2: sequential scan over L. 128 blocks x 4 batch rows, 256 threads.
// Thread s owns output state s for its 4 rows.
// ---------------------------------------------------------------------------
#define ROWS 4

__global__ __launch_bounds__(256) void scan_kernel(
    const float* __restrict__ Wss1,   // SA x SA
    const float* __restrict__ Wss2,   // SA x SA
    const float* __restrict__ tr1,    // SA x R
    const float* __restrict__ tw,     // SA x SA (wildcard)
    const float* __restrict__ h1,     // SA
    float*       __restrict__ out)    // B x L x SA
{
    __shared__ float s_h   [ROWS * SAA];
    __shared__ float s_hbar[ROWS * SAA];
    __shared__ float s_LRv [ROWS * RR];
    __shared__ float s_Lt  [ROWS * RR];

    const int s  = threadIdx.x;
    const int b0 = blockIdx.x * ROWS;
    const float h1s = h1[s];

    float hreg[ROWS];
#pragma unroll
    for (int t = 0; t < ROWS; t++) {
        float v = (s == 0) ? 1.0f : 0.0f;
        hreg[t] = v;
        s_h[t * SAA + s] = v;
    }
    __syncthreads();

    const float4* s_h4    = reinterpret_cast<const float4*>(s_h);
    const float4* s_hbar4 = reinterpret_cast<const float4*>(s_hbar);
    const float4* s_LRv4  = reinterpret_cast<const float4*>(s_LRv);

    for (int l = 0; l < LL; l++) {
        // --- Step 1: gates. az/ar init from precomputed Lt@Wrs + bias ---
        float az[ROWS], ar[ROWS];
#pragma unroll
        for (int t = 0; t < ROWS; t++) {
            long base = ((long)(b0 + t) * LL + l) * 256 + s;
            s_Lt[t * RR + s] = g_Lseq[base];
            az[t] = g_G1[base];
            ar[t] = g_G2[base];
        }

        for (int k4 = 0; k4 < SAA / 4; k4++) {
            int k = k4 * 4;
            float w1a = Wss1[(k + 0) * SAA + s];
            float w1b = Wss1[(k + 1) * SAA + s];
            float w1c = Wss1[(k + 2) * SAA + s];
            float w1d = Wss1[(k + 3) * SAA + s];
            float w2a = Wss2[(k + 0) * SAA + s];
            float w2b = Wss2[(k + 1) * SAA + s];
            float w2c = Wss2[(k + 2) * SAA + s];
            float w2d = Wss2[(k + 3) * SAA + s];
#pragma unroll
            for (int t = 0; t < ROWS; t++) {
                float4 hv = s_h4[t * 64 + k4];
                az[t] += hv.x * w1a + hv.y * w1b + hv.z * w1c + hv.w * w1d;
                ar[t] += hv.x * w2a + hv.y * w2b + hv.z * w2c + hv.w * w2d;
            }
        }

        float zt[ROWS];
#pragma unroll
        for (int t = 0; t < ROWS; t++) {
            float z  = sigmoid_f(az[t]);
            float rr = sigmoid_f(ar[t]);
            zt[t] = z;
            float hb = (1.0f - rr) * h1s + rr * hreg[t];
            s_hbar[t * SAA + s] = hb;
        }
        __syncthreads();

        // --- Step 2: Rv = hbar @ tr1; LRv = Lt * Rv ---
        float av[ROWS];
#pragma unroll
        for (int t = 0; t < ROWS; t++) av[t] = 0.0f;

        for (int k4 = 0; k4 < SAA / 4; k4++) {
            int k = k4 * 4;
            float w0 = tr1[(k + 0) * RR + s];
            float w1 = tr1[(k + 1) * RR + s];
            float w2 = tr1[(k + 2) * RR + s];
            float w3 = tr1[(k + 3) * RR + s];
#pragma unroll
            for (int t = 0; t < ROWS; t++) {
                float4 hb = s_hbar4[t * 64 + k4];
                av[t] += hb.x * w0 + hb.y * w1 + hb.z * w2 + hb.w * w3;
            }
        }
#pragma unroll
        for (int t = 0; t < ROWS; t++) {
            s_LRv[t * RR + s] = av[t] * s_Lt[t * RR + s];
        }
        __syncthreads();

        // --- Step 3: hid = relu(LRv @ tr2^T + hbar @ tw); blend ---
        float ah[ROWS];
#pragma unroll
        for (int t = 0; t < ROWS; t++) ah[t] = 0.0f;

        for (int k4 = 0; k4 < RR / 4; k4++) {
            int k = k4 * 4;
            float u0 = g_t2T[(k + 0) * SAA + s];
            float u1 = g_t2T[(k + 1) * SAA + s];
            float u2 = g_t2T[(k + 2) * SAA + s];
            float u3 = g_t2T[(k + 3) * SAA + s];
            float v0 = tw[(k + 0) * SAA + s];
            float v1 = tw[(k + 1) * SAA + s];
            float v2 = tw[(k + 2) * SAA + s];
            float v3 = tw[(k + 3) * SAA + s];
#pragma unroll
            for (int t = 0; t < ROWS; t++) {
                float4 lr = s_LRv4[t * 64 + k4];
                float4 hb = s_hbar4[t * 64 + k4];
                ah[t] += lr.x * u0 + lr.y * u1 + lr.z * u2 + lr.w * u3;
                ah[t] += hb.x * v0 + hb.y * v1 + hb.z * v2 + hb.w * v3;
            }
        }

#pragma unroll
        for (int t = 0; t < ROWS; t++) {
            float hid = fmaxf(ah[t], 0.0f);
            float hn  = (1.0f - zt[t]) * hreg[t] + zt[t] * hid;
            hreg[t] = hn;
            s_h[t * SAA + s] = hn;
            out[((long)(b0 + t) * LL + l) * SAA + s] = hn;
        }
        __syncthreads();
    }
}

// ---------------------------------------------------------------------------
// Launch
// ---------------------------------------------------------------------------
extern "C" void kernel_launch(void* const* d_in, const int* in_sizes, int n_in,
                              void* d_out, int out_size) {
    const int*   ids       = (const int*)  d_in[0];
    // d_in[1] = lengths (unused by the reference forward)
    const float* embedding = (const float*)d_in[2];
    const float* embed_r   = (const float*)d_in[3];
    const float* erg       = (const float*)d_in[4];
    const float* Wss1      = (const float*)d_in[5];
    const float* Wrs1      = (const float*)d_in[6];
    const float* bs1       = (const float*)d_in[7];
    const float* Wss2      = (const float*)d_in[8];
    const float* Wrs2      = (const float*)d_in[9];
    const float* bs2       = (const float*)d_in[10];
    const float* beta      = (const float*)d_in[11];
    const float* tw        = (const float*)d_in[12];
    const float* tr1       = (const float*)d_in[13];
    const float* tr2       = (const float*)d_in[14];
    const float* h1        = (const float*)d_in[15];
    float* out = (float*)d_out;

    transpose_tr2<<<256, 256>>>(tr2);
    precompute_kernel<<<(BB * LL) / TOK, 256>>>(ids, embedding, embed_r, erg,
                                                Wrs1, bs1, Wrs2, bs2, beta);
    scan_kernel<<<BB / ROWS, 256>>>(Wss1, Wss2, tr1, tw, h1, out);
}

// round 4
// speedup vs baseline: 1.0361x; 1.0361x over previous
#include <cuda_runtime.h>
#include <cuda_bf16.h>
#include <math.h>

// Problem constants
#define BB   512
#define LL   128
#define DD   300
#define RR   256
#define SAA  256

typedef unsigned long long ull;

// ---------------------------------------------------------------------------
// Scratch (device globals — no allocation allowed)
// ---------------------------------------------------------------------------
__device__ float g_Lseq[(size_t)BB * LL * RR];   // 67 MB
__device__ float g_G1  [(size_t)BB * LL * SAA]; // 67 MB
__device__ float g_G2  [(size_t)BB * LL * SAA]; // 67 MB

// Packed weights: P[k4*256 + s] = {W[4k4+0][s], W[4k4+1][s], W[4k4+2][s], W[4k4+3][s]}
__device__ float4 g_Pw1 [64 * 256];   // Wss1
__device__ float4 g_Pw2 [64 * 256];   // Wss2
__device__ float4 g_PwrA[64 * 256];   // Wrs1
__device__ float4 g_PwrB[64 * 256];   // Wrs2
__device__ float4 g_Pt1 [64 * 256];   // trans_r1
__device__ float4 g_Ptw [64 * 256];   // trans_wildcard
__device__ float4 g_Pt2 [64 * 256];   // trans_r2^T  (Pt2[k4][s] = tr2[s][4k4..4k4+3])
__device__ float4 g_Perg[75 * 256];   // embed_r_gen (D=300 -> 75 k4 groups)

// ---------------------------------------------------------------------------
// f32x2 packed-fp32 helpers
// ---------------------------------------------------------------------------
__device__ __forceinline__ void ffma2(ull &acc, ull a, ull b) {
    asm("fma.rn.f32x2 %0, %1, %2, %0;" : "+l"(acc) : "l"(a), "l"(b));
}
__device__ __forceinline__ ull pack2(float lo, float hi) {
    ull r; asm("mov.b64 %0, {%1, %2};" : "=l"(r) : "f"(lo), "f"(hi)); return r;
}
__device__ __forceinline__ float sum2(ull v) {
    float a, b; asm("mov.b64 {%0, %1}, %2;" : "=f"(a), "=f"(b) : "l"(v));
    return a + b;
}

__device__ __forceinline__ float sigmoid_f(float x) {
    return 1.0f / (1.0f + __expf(-x));
}
__device__ __forceinline__ float tanh_f(float x) {
    return 1.0f - 2.0f / (__expf(2.0f * x) + 1.0f);
}

// ---------------------------------------------------------------------------
// Kernel 0: pack all weight matrices into float4-over-k layout.
// grid = 8 * 75 blocks, 256 threads. m=0 -> erg (75 groups), m=1..7 -> 64 groups.
// ---------------------------------------------------------------------------
__global__ __launch_bounds__(256) void pack_weights(
    const float* __restrict__ Wss1, const float* __restrict__ Wss2,
    const float* __restrict__ Wrs1, const float* __restrict__ Wrs2,
    const float* __restrict__ tr1,  const float* __restrict__ tw,
    const float* __restrict__ tr2,  const float* __restrict__ erg)
{
    const int bx = blockIdx.x;
    const int m  = bx / 75;
    const int k4 = bx % 75;
    const int s  = threadIdx.x;

    if (m == 0) {
        // erg: D x R, 75 groups
        g_Perg[k4 * 256 + s] = make_float4(
            erg[(4 * k4 + 0) * RR + s], erg[(4 * k4 + 1) * RR + s],
            erg[(4 * k4 + 2) * RR + s], erg[(4 * k4 + 3) * RR + s]);
        return;
    }
    if (k4 >= 64) return;

    const int k = 4 * k4;
    switch (m) {
        case 1: g_Pw1 [k4 * 256 + s] = make_float4(Wss1[(k+0)*SAA+s], Wss1[(k+1)*SAA+s], Wss1[(k+2)*SAA+s], Wss1[(k+3)*SAA+s]); break;
        case 2: g_Pw2 [k4 * 256 + s] = make_float4(Wss2[(k+0)*SAA+s], Wss2[(k+1)*SAA+s], Wss2[(k+2)*SAA+s], Wss2[(k+3)*SAA+s]); break;
        case 3: g_PwrA[k4 * 256 + s] = make_float4(Wrs1[(k+0)*SAA+s], Wrs1[(k+1)*SAA+s], Wrs1[(k+2)*SAA+s], Wrs1[(k+3)*SAA+s]); break;
        case 4: g_PwrB[k4 * 256 + s] = make_float4(Wrs2[(k+0)*SAA+s], Wrs2[(k+1)*SAA+s], Wrs2[(k+2)*SAA+s], Wrs2[(k+3)*SAA+s]); break;
        case 5: g_Pt1 [k4 * 256 + s] = make_float4(tr1 [(k+0)*RR +s], tr1 [(k+1)*RR +s], tr1 [(k+2)*RR +s], tr1 [(k+3)*RR +s]); break;
        case 6: g_Ptw [k4 * 256 + s] = make_float4(tw  [(k+0)*SAA+s], tw  [(k+1)*SAA+s], tw  [(k+2)*SAA+s], tw  [(k+3)*SAA+s]); break;
        case 7: g_Pt2 [k4 * 256 + s] = *reinterpret_cast<const float4*>(&tr2[s * RR + k]); break;  // transpose fold
    }
}

// ---------------------------------------------------------------------------
// Kernel 1: token-parallel precompute (TOK=16 tokens/block, 256 threads).
//   Lseq = embed_r[id]*beta + tanh(emb[id] @ erg)*(1-beta)
//   G1/G2 = Lseq @ Wrs{1,2} + bias
// k-pair FFMA2 everywhere.
// ---------------------------------------------------------------------------
#define TOK 16

__global__ __launch_bounds__(256) void precompute_kernel(
    const int*   __restrict__ ids,
    const float* __restrict__ embedding,   // V x D
    const float* __restrict__ embed_r,     // V x R
    const float* __restrict__ bs1,
    const float* __restrict__ bs2,
    const float* __restrict__ beta)
{
    __shared__ int   s_id[TOK];
    __shared__ float s_emb[TOK * 304];     // D=300 padded to 304 (16B align/row)
    __shared__ float s_Lt[TOK * RR];

    const int tid  = threadIdx.x;
    const int tok0 = blockIdx.x * TOK;

    if (tid < TOK) s_id[tid] = ids[tok0 + tid];
    __syncthreads();

    for (int i = tid; i < TOK * DD; i += 256) {
        int t = i / DD;
        int d = i - t * DD;
        s_emb[t * 304 + d] = embedding[(long)s_id[t] * DD + d];
    }
    __syncthreads();

    const int r = tid;
    const float beta_r = beta[r];

    // Phase 1: Lg = tanh(emb @ erg)
    ull acc[TOK];
#pragma unroll
    for (int t = 0; t < TOK; t++) acc[t] = 0ULL;

#pragma unroll 5
    for (int d4 = 0; d4 < 75; d4++) {
        ulonglong2 w = *reinterpret_cast<const ulonglong2*>(&g_Perg[d4 * 256 + r]);
#pragma unroll
        for (int t = 0; t < TOK; t++) {
            ulonglong2 e = *reinterpret_cast<const ulonglong2*>(&s_emb[t * 304 + 4 * d4]);
            ffma2(acc[t], e.x, w.x);
            ffma2(acc[t], e.y, w.y);
        }
    }

#pragma unroll
    for (int t = 0; t < TOK; t++) {
        float lg = tanh_f(sum2(acc[t]));
        float er = embed_r[(long)s_id[t] * RR + r];
        float v  = er * beta_r + lg * (1.0f - beta_r);
        s_Lt[t * RR + r] = v;
        g_Lseq[(long)(tok0 + t) * RR + r] = v;
    }
    __syncthreads();

    // Phase 2: G1/G2
    ull a1[TOK], a2[TOK];
    const float b1v = bs1[r];
    const float b2v = bs2[r];
#pragma unroll
    for (int t = 0; t < TOK; t++) { a1[t] = pack2(b1v, 0.0f); a2[t] = pack2(b2v, 0.0f); }

#pragma unroll 4
    for (int k4 = 0; k4 < 64; k4++) {
        ulonglong2 w1 = *reinterpret_cast<const ulonglong2*>(&g_PwrA[k4 * 256 + r]);
        ulonglong2 w2 = *reinterpret_cast<const ulonglong2*>(&g_PwrB[k4 * 256 + r]);
#pragma unroll
        for (int t = 0; t < TOK; t++) {
            ulonglong2 lv = *reinterpret_cast<const ulonglong2*>(&s_Lt[t * RR + 4 * k4]);
            ffma2(a1[t], lv.x, w1.x);
            ffma2(a1[t], lv.y, w1.y);
            ffma2(a2[t], lv.x, w2.x);
            ffma2(a2[t], lv.y, w2.y);
        }
    }

#pragma unroll
    for (int t = 0; t < TOK; t++) {
        g_G1[(long)(tok0 + t) * SAA + r] = sum2(a1[t]);
        g_G2[(long)(tok0 + t) * SAA + r] = sum2(a2[t]);
    }
}

// ---------------------------------------------------------------------------
// Kernel 2: sequential scan. 64 CTAs x 8 batch rows, 512 threads.
// Thread = (state s, row-group of 4). FFMA2 over k-pairs; float4 weight LDGs.
// ---------------------------------------------------------------------------
#define ROWS 8

__global__ __launch_bounds__(512) void scan_kernel(
    const float* __restrict__ h1,     // SA
    float*       __restrict__ out)    // B x L x SA
{
    __shared__ float s_h   [ROWS * SAA];
    __shared__ float s_hbar[ROWS * SAA];
    __shared__ float s_LRv [ROWS * RR];

    const int s   = threadIdx.x & 255;
    const int grp = threadIdx.x >> 8;       // 0..1
    const int r0  = grp * 4;                // first row of this thread's group
    const int b0  = blockIdx.x * ROWS;
    const float h1s = h1[s];

    float hreg[4];
#pragma unroll
    for (int t = 0; t < 4; t++) {
        float v = (s == 0) ? 1.0f : 0.0f;
        hreg[t] = v;
        s_h[(r0 + t) * SAA + s] = v;
    }
    __syncthreads();

    for (int l = 0; l < LL; l++) {
        // --- Phase 1: gates ---
        ull az[4], ar[4];
        float lt[4];
#pragma unroll
        for (int t = 0; t < 4; t++) {
            long base = ((long)(b0 + r0 + t) * LL + l) * 256 + s;
            lt[t] = g_Lseq[base];
            az[t] = pack2(g_G1[base], 0.0f);
            ar[t] = pack2(g_G2[base], 0.0f);
        }

#pragma unroll 8
        for (int k4 = 0; k4 < 64; k4++) {
            ulonglong2 w1 = *reinterpret_cast<const ulonglong2*>(&g_Pw1[k4 * 256 + s]);
            ulonglong2 w2 = *reinterpret_cast<const ulonglong2*>(&g_Pw2[k4 * 256 + s]);
#pragma unroll
            for (int t = 0; t < 4; t++) {
                ulonglong2 hv = *reinterpret_cast<const ulonglong2*>(&s_h[(r0 + t) * SAA + 4 * k4]);
                ffma2(az[t], hv.x, w1.x);
                ffma2(az[t], hv.y, w1.y);
                ffma2(ar[t], hv.x, w2.x);
                ffma2(ar[t], hv.y, w2.y);
            }
        }

        float zt[4];
#pragma unroll
        for (int t = 0; t < 4; t++) {
            float z  = sigmoid_f(sum2(az[t]));
            float rr = sigmoid_f(sum2(ar[t]));
            zt[t] = z;
            s_hbar[(r0 + t) * SAA + s] = (1.0f - rr) * h1s + rr * hreg[t];
        }
        __syncthreads();

        // --- Phase 2: Rv = hbar @ tr1; LRv = Lt * Rv ---
        ull av[4];
#pragma unroll
        for (int t = 0; t < 4; t++) av[t] = 0ULL;

#pragma unroll 8
        for (int k4 = 0; k4 < 64; k4++) {
            ulonglong2 w = *reinterpret_cast<const ulonglong2*>(&g_Pt1[k4 * 256 + s]);
#pragma unroll
            for (int t = 0; t < 4; t++) {
                ulonglong2 hb = *reinterpret_cast<const ulonglong2*>(&s_hbar[(r0 + t) * SAA + 4 * k4]);
                ffma2(av[t], hb.x, w.x);
                ffma2(av[t], hb.y, w.y);
            }
        }
#pragma unroll
        for (int t = 0; t < 4; t++) {
            s_LRv[(r0 + t) * RR + s] = sum2(av[t]) * lt[t];
        }
        __syncthreads();

        // --- Phase 3: hid = relu(LRv @ tr2^T + hbar @ tw); blend ---
        ull ah[4];
#pragma unroll
        for (int t = 0; t < 4; t++) ah[t] = 0ULL;

#pragma unroll 4
        for (int k4 = 0; k4 < 64; k4++) {
            ulonglong2 wu = *reinterpret_cast<const ulonglong2*>(&g_Pt2[k4 * 256 + s]);
            ulonglong2 wv = *reinterpret_cast<const ulonglong2*>(&g_Ptw[k4 * 256 + s]);
#pragma unroll
            for (int t = 0; t < 4; t++) {
                ulonglong2 lr = *reinterpret_cast<const ulonglong2*>(&s_LRv [(r0 + t) * RR  + 4 * k4]);
                ulonglong2 hb = *reinterpret_cast<const ulonglong2*>(&s_hbar[(r0 + t) * SAA + 4 * k4]);
                ffma2(ah[t], lr.x, wu.x);
                ffma2(ah[t], lr.y, wu.y);
                ffma2(ah[t], hb.x, wv.x);
                ffma2(ah[t], hb.y, wv.y);
            }
        }

#pragma unroll
        for (int t = 0; t < 4; t++) {
            float hid = fmaxf(sum2(ah[t]), 0.0f);
            float hn  = (1.0f - zt[t]) * hreg[t] + zt[t] * hid;
            hreg[t] = hn;
            s_h[(r0 + t) * SAA + s] = hn;
            out[((long)(b0 + r0 + t) * LL + l) * SAA + s] = hn;
        }
        __syncthreads();
    }
}

// ---------------------------------------------------------------------------
// Launch
// ---------------------------------------------------------------------------
extern "C" void kernel_launch(void* const* d_in, const int* in_sizes, int n_in,
                              void* d_out, int out_size) {
    const int*   ids       = (const int*)  d_in[0];
    // d_in[1] = lengths (unused by the reference forward)
    const float* embedding = (const float*)d_in[2];
    const float* embed_r   = (const float*)d_in[3];
    const float* erg       = (const float*)d_in[4];
    const float* Wss1      = (const float*)d_in[5];
    const float* Wrs1      = (const float*)d_in[6];
    const float* bs1       = (const float*)d_in[7];
    const float* Wss2      = (const float*)d_in[8];
    const float* Wrs2      = (const float*)d_in[9];
    const float* bs2       = (const float*)d_in[10];
    const float* beta      = (const float*)d_in[11];
    const float* tw        = (const float*)d_in[12];
    const float* tr1       = (const float*)d_in[13];
    const float* tr2       = (const float*)d_in[14];
    const float* h1        = (const float*)d_in[15];
    float* out = (float*)d_out;

    pack_weights<<<8 * 75, 256>>>(Wss1, Wss2, Wrs1, Wrs2, tr1, tw, tr2, erg);
    precompute_kernel<<<(BB * LL) / TOK, 256>>>(ids, embedding, embed_r, bs1, bs2, beta);
    scan_kernel<<<BB / ROWS, 512>>>(h1, out);
}

// round 5
// speedup vs baseline: 1.1803x; 1.1392x over previous
#include <cuda_runtime.h>
#include <cuda_bf16.h>
#include <math.h>
#include <stdint.h>

// Problem constants
#define BB   512
#define LL   128
#define DD   300
#define RR   256
#define SAA  256

typedef unsigned long long ull;

// ---------------------------------------------------------------------------
// Scratch (device globals — no allocation allowed)
// ---------------------------------------------------------------------------
__device__ float g_Lseq[(size_t)BB * LL * RR];   // 67 MB
__device__ float g_G1  [(size_t)BB * LL * SAA]; // 67 MB
__device__ float g_G2  [(size_t)BB * LL * SAA]; // 67 MB

// Packed weights: P[k4*256 + s] = {W[4k4+0][s], .., W[4k4+3][s]}
__device__ float4 g_Pw1 [64 * 256];   // Wss1
__device__ float4 g_Pw2 [64 * 256];   // Wss2
__device__ float4 g_PwrA[64 * 256];   // Wrs1
__device__ float4 g_PwrB[64 * 256];   // Wrs2
__device__ float4 g_Pt1 [64 * 256];   // trans_r1
__device__ float4 g_Ptw [64 * 256];   // trans_wildcard (streamed from L2 in scan)
__device__ float4 g_Pt2 [64 * 256];   // trans_r2^T
__device__ float4 g_Perg[75 * 256];   // embed_r_gen

// ---------------------------------------------------------------------------
// f32x2 packed-fp32 helpers
// ---------------------------------------------------------------------------
__device__ __forceinline__ void ffma2(ull &acc, ull a, ull b) {
    asm("fma.rn.f32x2 %0, %1, %2, %0;" : "+l"(acc) : "l"(a), "l"(b));
}
__device__ __forceinline__ ull pack2(float lo, float hi) {
    ull r; asm("mov.b64 %0, {%1, %2};" : "=l"(r) : "f"(lo), "f"(hi)); return r;
}
__device__ __forceinline__ float sum2(ull v) {
    float a, b; asm("mov.b64 {%0, %1}, %2;" : "=f"(a), "=f"(b) : "l"(v));
    return a + b;
}
__device__ __forceinline__ float sigmoid_f(float x) {
    return 1.0f / (1.0f + __expf(-x));
}
__device__ __forceinline__ float tanh_f(float x) {
    return 1.0f - 2.0f / (__expf(2.0f * x) + 1.0f);
}

// Cluster helpers
__device__ __forceinline__ uint32_t smem_u32(const void* p) {
    uint32_t a;
    asm("{ .reg .u64 t; cvta.to.shared.u64 t, %1; cvt.u32.u64 %0, t; }" : "=r"(a) : "l"(p));
    return a;
}
__device__ __forceinline__ uint32_t mapa_u32(uint32_t saddr, int rank) {
    uint32_t r;
    asm("mapa.shared::cluster.u32 %0, %1, %2;" : "=r"(r) : "r"(saddr), "r"(rank));
    return r;
}
__device__ __forceinline__ void st_cluster_f32(uint32_t addr, float v) {
    asm volatile("st.shared::cluster.f32 [%0], %1;" :: "r"(addr), "f"(v) : "memory");
}
__device__ __forceinline__ void cluster_sync() {
    asm volatile("barrier.cluster.arrive.aligned;" ::: "memory");
    asm volatile("barrier.cluster.wait.aligned;" ::: "memory");
}
__device__ __forceinline__ uint32_t ctarank() {
    uint32_t r; asm("mov.u32 %0, %%cluster_ctarank;" : "=r"(r)); return r;
}

// ---------------------------------------------------------------------------
// Kernel 0: pack all weight matrices into float4-over-k layout.
// ---------------------------------------------------------------------------
__global__ __launch_bounds__(256) void pack_weights(
    const float* __restrict__ Wss1, const float* __restrict__ Wss2,
    const float* __restrict__ Wrs1, const float* __restrict__ Wrs2,
    const float* __restrict__ tr1,  const float* __restrict__ tw,
    const float* __restrict__ tr2,  const float* __restrict__ erg)
{
    const int bx = blockIdx.x;
    const int m  = bx / 75;
    const int k4 = bx % 75;
    const int s  = threadIdx.x;

    if (m == 0) {
        g_Perg[k4 * 256 + s] = make_float4(
            erg[(4 * k4 + 0) * RR + s], erg[(4 * k4 + 1) * RR + s],
            erg[(4 * k4 + 2) * RR + s], erg[(4 * k4 + 3) * RR + s]);
        return;
    }
    if (k4 >= 64) return;

    const int k = 4 * k4;
    switch (m) {
        case 1: g_Pw1 [k4 * 256 + s] = make_float4(Wss1[(k+0)*SAA+s], Wss1[(k+1)*SAA+s], Wss1[(k+2)*SAA+s], Wss1[(k+3)*SAA+s]); break;
        case 2: g_Pw2 [k4 * 256 + s] = make_float4(Wss2[(k+0)*SAA+s], Wss2[(k+1)*SAA+s], Wss2[(k+2)*SAA+s], Wss2[(k+3)*SAA+s]); break;
        case 3: g_PwrA[k4 * 256 + s] = make_float4(Wrs1[(k+0)*SAA+s], Wrs1[(k+1)*SAA+s], Wrs1[(k+2)*SAA+s], Wrs1[(k+3)*SAA+s]); break;
        case 4: g_PwrB[k4 * 256 + s] = make_float4(Wrs2[(k+0)*SAA+s], Wrs2[(k+1)*SAA+s], Wrs2[(k+2)*SAA+s], Wrs2[(k+3)*SAA+s]); break;
        case 5: g_Pt1 [k4 * 256 + s] = make_float4(tr1 [(k+0)*RR +s], tr1 [(k+1)*RR +s], tr1 [(k+2)*RR +s], tr1 [(k+3)*RR +s]); break;
        case 6: g_Ptw [k4 * 256 + s] = make_float4(tw  [(k+0)*SAA+s], tw  [(k+1)*SAA+s], tw  [(k+2)*SAA+s], tw  [(k+3)*SAA+s]); break;
        case 7: g_Pt2 [k4 * 256 + s] = *reinterpret_cast<const float4*>(&tr2[s * RR + k]); break;
    }
}

// ---------------------------------------------------------------------------
// Kernel 1: token-parallel precompute (unchanged structure).
// ---------------------------------------------------------------------------
#define TOK 16

__global__ __launch_bounds__(256) void precompute_kernel(
    const int*   __restrict__ ids,
    const float* __restrict__ embedding,
    const float* __restrict__ embed_r,
    const float* __restrict__ bs1,
    const float* __restrict__ bs2,
    const float* __restrict__ beta)
{
    __shared__ int   s_id[TOK];
    __shared__ float s_emb[TOK * 304];
    __shared__ float s_Lt[TOK * RR];

    const int tid  = threadIdx.x;
    const int tok0 = blockIdx.x * TOK;

    if (tid < TOK) s_id[tid] = ids[tok0 + tid];
    __syncthreads();

    for (int i = tid; i < TOK * DD; i += 256) {
        int t = i / DD;
        int d = i - t * DD;
        s_emb[t * 304 + d] = embedding[(long)s_id[t] * DD + d];
    }
    __syncthreads();

    const int r = tid;
    const float beta_r = beta[r];

    ull acc[TOK];
#pragma unroll
    for (int t = 0; t < TOK; t++) acc[t] = 0ULL;

#pragma unroll 5
    for (int d4 = 0; d4 < 75; d4++) {
        ulonglong2 w = *reinterpret_cast<const ulonglong2*>(&g_Perg[d4 * 256 + r]);
#pragma unroll
        for (int t = 0; t < TOK; t++) {
            ulonglong2 e = *reinterpret_cast<const ulonglong2*>(&s_emb[t * 304 + 4 * d4]);
            ffma2(acc[t], e.x, w.x);
            ffma2(acc[t], e.y, w.y);
        }
    }

#pragma unroll
    for (int t = 0; t < TOK; t++) {
        float lg = tanh_f(sum2(acc[t]));
        float er = embed_r[(long)s_id[t] * RR + r];
        float v  = er * beta_r + lg * (1.0f - beta_r);
        s_Lt[t * RR + r] = v;
        g_Lseq[(long)(tok0 + t) * RR + r] = v;
    }
    __syncthreads();

    ull a1[TOK], a2[TOK];
    const float b1v = bs1[r];
    const float b2v = bs2[r];
#pragma unroll
    for (int t = 0; t < TOK; t++) { a1[t] = pack2(b1v, 0.0f); a2[t] = pack2(b2v, 0.0f); }

#pragma unroll 4
    for (int k4 = 0; k4 < 64; k4++) {
        ulonglong2 w1 = *reinterpret_cast<const ulonglong2*>(&g_PwrA[k4 * 256 + r]);
        ulonglong2 w2 = *reinterpret_cast<const ulonglong2*>(&g_PwrB[k4 * 256 + r]);
#pragma unroll
        for (int t = 0; t < TOK; t++) {
            ulonglong2 lv = *reinterpret_cast<const ulonglong2*>(&s_Lt[t * RR + 4 * k4]);
            ffma2(a1[t], lv.x, w1.x);
            ffma2(a1[t], lv.y, w1.y);
            ffma2(a2[t], lv.x, w2.x);
            ffma2(a2[t], lv.y, w2.y);
        }
    }

#pragma unroll
    for (int t = 0; t < TOK; t++) {
        g_G1[(long)(tok0 + t) * SAA + r] = sum2(a1[t]);
        g_G2[(long)(tok0 + t) * SAA + r] = sum2(a2[t]);
    }
}

// ---------------------------------------------------------------------------
// Kernel 2: clustered scan.
// 16 clusters x 8 CTAs; cluster owns 32 batch rows; CTA owns 32 state columns
// with its weight slices resident in SMEM. State vectors exchanged via DSMEM.
//
// SMEM layout (dynamic, 224 KB):
//   A  : h      [32 rows][256]   (P3 writes new h here; P1 reads)
//   Bf : hbar   [32 rows][256]   (P1 writes; P2/P3 read)
//   C  : LRv    [32 rows][256]   (P2 writes; P3 reads)
//   w1,w2,t1,t2: [64 k4][32 col] float4 slices
// ---------------------------------------------------------------------------
#define OFF_A   0
#define OFF_B   8192
#define OFF_C   16384
#define OFF_W1  24576
#define OFF_W2  (24576 + 8192)
#define OFF_T1  (24576 + 16384)
#define OFF_T2  (24576 + 24576)
#define SMEM_FLOATS (24576 + 32768)          // 57344 floats = 229376 bytes

__global__ void __cluster_dims__(8, 1, 1) __launch_bounds__(256, 1)
scan_kernel(const float* __restrict__ h1, float* __restrict__ out)
{
    extern __shared__ float sm[];
    float*  A  = sm + OFF_A;
    float*  Bf = sm + OFF_B;
    float*  C  = sm + OFF_C;
    float4* w1 = reinterpret_cast<float4*>(sm + OFF_W1);
    float4* w2 = reinterpret_cast<float4*>(sm + OFF_W2);
    float4* t1 = reinterpret_cast<float4*>(sm + OFF_T1);
    float4* t2 = reinterpret_cast<float4*>(sm + OFF_T2);

    const int tid  = threadIdx.x;
    const int col  = tid & 31;                 // lane = local column
    const int grp  = tid >> 5;                 // warp = row group (4 rows)
    const uint32_t rank = ctarank();
    const int sg   = (int)rank * 32 + col;     // global state column
    const int b0   = (blockIdx.x >> 3) * 32;   // cluster's first batch row

    // DSMEM bases for all 8 peer CTAs
    uint32_t base_local = smem_u32(sm);
    uint32_t peer[8];
#pragma unroll
    for (int d = 0; d < 8; d++) peer[d] = mapa_u32(base_local, d);

    // Load weight slices (cols [rank*32, rank*32+32)) into SMEM
    for (int i = tid; i < 2048; i += 256) {
        int k4 = i >> 5, c = i & 31;
        int gidx = k4 * 256 + (int)rank * 32 + c;
        w1[i] = g_Pw1[gidx];
        w2[i] = g_Pw2[gidx];
        t1[i] = g_Pt1[gidx];
        t2[i] = g_Pt2[gidx];
    }
    // Init h0 (full width, locally)
    for (int i = tid; i < 8192; i += 256) A[i] = ((i & 255) == 0) ? 1.0f : 0.0f;
    __syncthreads();

    const float h1s = h1[sg];
    float hreg[4];
#pragma unroll
    for (int t = 0; t < 4; t++) hreg[t] = (sg == 0) ? 1.0f : 0.0f;

    // make sure every CTA finished init before anyone's P3 pushes arrive later;
    // also rendezvous before first remote writes
    cluster_sync();

    for (int l = 0; l < LL; l++) {
        // ---------------- Phase 1: gates + hbar ----------------
        ull az[4], ar[4];
#pragma unroll
        for (int t = 0; t < 4; t++) {
            long gb = ((long)(b0 + grp * 4 + t) * LL + l) * 256 + sg;
            az[t] = pack2(g_G1[gb], 0.0f);
            ar[t] = pack2(g_G2[gb], 0.0f);
        }

#pragma unroll 4
        for (int k4 = 0; k4 < 64; k4++) {
            ulonglong2 W1 = *reinterpret_cast<const ulonglong2*>(&w1[k4 * 32 + col]);
            ulonglong2 W2 = *reinterpret_cast<const ulonglong2*>(&w2[k4 * 32 + col]);
#pragma unroll
            for (int t = 0; t < 4; t++) {
                ulonglong2 hv = *reinterpret_cast<const ulonglong2*>(&A[(grp * 4 + t) * 256 + k4 * 4]);
                ffma2(az[t], hv.x, W1.x);
                ffma2(az[t], hv.y, W1.y);
                ffma2(ar[t], hv.x, W2.x);
                ffma2(ar[t], hv.y, W2.y);
            }
        }

        float zt[4];
#pragma unroll
        for (int t = 0; t < 4; t++) {
            float z  = sigmoid_f(sum2(az[t]));
            float rr = sigmoid_f(sum2(ar[t]));
            zt[t] = z;
            float hb = (1.0f - rr) * h1s + rr * hreg[t];
            uint32_t off = (OFF_B + (grp * 4 + t) * 256 + sg) * 4u;
#pragma unroll
            for (int d = 0; d < 8; d++) st_cluster_f32(peer[d] + off, hb);
        }
        cluster_sync();

        // ---------------- Phase 2: Rv = hbar @ tr1; LRv = Lt * Rv ----------------
        ull av[4];
        float ltv[4];
#pragma unroll
        for (int t = 0; t < 4; t++) {
            av[t] = 0ULL;
            ltv[t] = g_Lseq[((long)(b0 + grp * 4 + t) * LL + l) * 256 + sg];
        }

#pragma unroll 4
        for (int k4 = 0; k4 < 64; k4++) {
            ulonglong2 W = *reinterpret_cast<const ulonglong2*>(&t1[k4 * 32 + col]);
#pragma unroll
            for (int t = 0; t < 4; t++) {
                ulonglong2 hb = *reinterpret_cast<const ulonglong2*>(&Bf[(grp * 4 + t) * 256 + k4 * 4]);
                ffma2(av[t], hb.x, W.x);
                ffma2(av[t], hb.y, W.y);
            }
        }

#pragma unroll
        for (int t = 0; t < 4; t++) {
            float lrv = sum2(av[t]) * ltv[t];
            uint32_t off = (OFF_C + (grp * 4 + t) * 256 + sg) * 4u;
#pragma unroll
            for (int d = 0; d < 8; d++) st_cluster_f32(peer[d] + off, lrv);
        }
        cluster_sync();

        // ---------------- Phase 3: hid = relu(LRv @ t2 + hbar @ tw); blend ----------------
        ull ah[4];
#pragma unroll
        for (int t = 0; t < 4; t++) ah[t] = 0ULL;

#pragma unroll 4
        for (int k4 = 0; k4 < 64; k4++) {
            ulonglong2 Wu = *reinterpret_cast<const ulonglong2*>(&t2[k4 * 32 + col]);
            ulonglong2 Wv = *reinterpret_cast<const ulonglong2*>(&g_Ptw[k4 * 256 + sg]);
#pragma unroll
            for (int t = 0; t < 4; t++) {
                ulonglong2 lr = *reinterpret_cast<const ulonglong2*>(&C [(grp * 4 + t) * 256 + k4 * 4]);
                ulonglong2 hb = *reinterpret_cast<const ulonglong2*>(&Bf[(grp * 4 + t) * 256 + k4 * 4]);
                ffma2(ah[t], lr.x, Wu.x);
                ffma2(ah[t], lr.y, Wu.y);
                ffma2(ah[t], hb.x, Wv.x);
                ffma2(ah[t], hb.y, Wv.y);
            }
        }

#pragma unroll
        for (int t = 0; t < 4; t++) {
            float hid = fmaxf(sum2(ah[t]), 0.0f);
            float hn  = (1.0f - zt[t]) * hreg[t] + zt[t] * hid;
            hreg[t] = hn;
            uint32_t off = (OFF_A + (grp * 4 + t) * 256 + sg) * 4u;
#pragma unroll
            for (int d = 0; d < 8; d++) st_cluster_f32(peer[d] + off, hn);
            out[((long)(b0 + grp * 4 + t) * LL + l) * SAA + sg] = hn;
        }
        cluster_sync();
    }
}

// ---------------------------------------------------------------------------
// Launch
// ---------------------------------------------------------------------------
extern "C" void kernel_launch(void* const* d_in, const int* in_sizes, int n_in,
                              void* d_out, int out_size) {
    const int*   ids       = (const int*)  d_in[0];
    const float* embedding = (const float*)d_in[2];
    const float* embed_r   = (const float*)d_in[3];
    const float* erg       = (const float*)d_in[4];
    const float* Wss1      = (const float*)d_in[5];
    const float* Wrs1      = (const float*)d_in[6];
    const float* bs1       = (const float*)d_in[7];
    const float* Wss2      = (const float*)d_in[8];
    const float* Wrs2      = (const float*)d_in[9];
    const float* bs2       = (const float*)d_in[10];
    const float* beta      = (const float*)d_in[11];
    const float* tw        = (const float*)d_in[12];
    const float* tr1       = (const float*)d_in[13];
    const float* tr2       = (const float*)d_in[14];
    const float* h1        = (const float*)d_in[15];
    float* out = (float*)d_out;

    static bool attr_done = false;
    if (!attr_done) {
        cudaFuncSetAttribute(scan_kernel,
                             cudaFuncAttributeMaxDynamicSharedMemorySize,
                             SMEM_FLOATS * sizeof(float));
        attr_done = true;
    }

    pack_weights<<<8 * 75, 256>>>(Wss1, Wss2, Wrs1, Wrs2, tr1, tw, tr2, erg);
    precompute_kernel<<<(BB * LL) / TOK, 256>>>(ids, embedding, embed_r, bs1, bs2, beta);
    scan_kernel<<<128, 256, SMEM_FLOATS * sizeof(float)>>>(h1, out);
}